// round 9
// baseline (speedup 1.0000x reference)
#include <cuda_runtime.h>
#include <cstdint>

// BaseEncoder: out[b, f, c] = (bitcast<u32>(x[b,f]) >> (31 - c)) & 1  (float).
// c==0 is bit 31 (sign == (x<0) channel); c>=1 are bits 30..0 of |x|.
//
// Bound analysis (R8 ncu): total L2-crossing traffic 264 MB in 41.9 us =
// 6.3 TB/s ~= 91% of the B300 LTS cap (~6300 B/cyc, path-independent).
// Remaining headroom is scheduling bubbles only. This version:
//   - persistent grid (no wave transitions, no tail-wave imbalance)
//   - double-buffered front-batched LDGs (next chunk's loads issued before
//     current chunk's stores -> load latency never exposed in steady state)
//   - per-warp stores stay perfectly coalesced: 512 contiguous B per STG.128.

constexpr int THREADS = 256;
constexpr int ITERS   = 8;                  // float4s per thread per chunk
constexpr int CHUNK   = THREADS * ITERS;    // 2048 float4s = 32 KB per chunk
constexpr int WSTRIDE = THREADS / 8;        // input words per iteration step

__global__ void __launch_bounds__(THREADS)
base_encoder_kernel(const uint32_t* __restrict__ x,
                    float4* __restrict__ out,
                    int n4, int nChunks)
{
    const uint32_t ONE = 0x3f800000u;       // bit pattern of 1.0f
    const int tid = threadIdx.x;
    const int c0  = (tid & 7) * 4;          // loop-invariant bit-channel base

    int chunk = blockIdx.x;
    if (chunk >= nChunks) return;

    // ---- prologue: load batch for first chunk ----
    uint32_t ucur[ITERS];
    {
        int w0 = (chunk * CHUNK + tid) >> 3;
        #pragma unroll
        for (int i = 0; i < ITERS; i++)
            ucur[i] = __ldg(&x[w0 + i * WSTRIDE]);
    }

    while (true) {
        int next = chunk + gridDim.x;

        // ---- issue next chunk's loads before storing current ----
        uint32_t unxt[ITERS];
        bool have_next = (next < nChunks);
        if (have_next) {
            int w0 = (next * CHUNK + tid) >> 3;
            #pragma unroll
            for (int i = 0; i < ITERS; i++)
                unxt[i] = __ldg(&x[w0 + i * WSTRIDE]);
        }

        // ---- compute + store current chunk (data already resident) ----
        int t0 = chunk * CHUNK + tid;
        #pragma unroll
        for (int i = 0; i < ITERS; i++) {
            uint32_t base = ucur[i] << c0;  // bit 31 of base == channel c0
            float4 v;
            v.x = __uint_as_float( (base >> 31)       * ONE);
            v.y = __uint_as_float(((base >> 30) & 1u) * ONE);
            v.z = __uint_as_float(((base >> 29) & 1u) * ONE);
            v.w = __uint_as_float(((base >> 28) & 1u) * ONE);
            out[t0 + i * THREADS] = v;
        }

        if (!have_next) break;
        #pragma unroll
        for (int i = 0; i < ITERS; i++) ucur[i] = unxt[i];
        chunk = next;
    }
}

extern "C" void kernel_launch(void* const* d_in, const int* in_sizes, int n_in,
                              void* d_out, int out_size)
{
    const uint32_t* x = (const uint32_t*)d_in[0];
    float4* out = (float4*)d_out;

    int n4 = out_size / 4;                  // 16,777,216 for 4096x512x32
    int nChunks = n4 / CHUNK;               // 8192 (shape is an exact multiple)

    // Persistent grid: 148 SMs x 8 CTAs. Each CTA walks chunks gridDim apart.
    int blocks = 148 * 8;
    if (blocks > nChunks) blocks = nChunks;

    base_encoder_kernel<<<blocks, THREADS>>>(x, out, n4, nChunks);
}

// round 10
// speedup vs baseline: 1.1341x; 1.1341x over previous
#include <cuda_runtime.h>
#include <cstdint>

// BaseEncoder: out[b, f, c] = (bitcast<u32>(x[b,f]) >> (31 - c)) & 1  (float).
// c==0 is bit 31 (sign == (x<0) channel); c>=1 are bits 30..0 of |x|.
//
// R8 analysis: 264 MB crosses the SM<->L2 interface in ~41.9 us = 6.3 TB/s,
// i.e. at the measured B300 LTS chip cap (~6300 B/cyc, path-independent).
// Structure (proven in R8): each block owns a contiguous chunk of
// THREADS*ITERS float4s; each thread front-batches ITERS independent LDGs
// (MLP=8), then computes + stores. Warp stores are 512 contiguous bytes per
// STG.128. Dynamic grid (no persistence) keeps HW work-stealing for balance.
// This round: THREADS 256->128 for finer CTA granularity / smoother store
// interleave; mapping otherwise identical.

constexpr int THREADS = 128;
constexpr int ITERS   = 8;                  // float4s per thread per chunk
constexpr int CHUNK   = THREADS * ITERS;    // 1024 float4s = 16 KB per block
constexpr int WSTRIDE = THREADS / 8;        // input words per iteration step

__global__ void __launch_bounds__(THREADS)
base_encoder_kernel(const uint32_t* __restrict__ x,
                    float4* __restrict__ out,
                    int n4)
{
    const uint32_t ONE = 0x3f800000u;       // bit pattern of 1.0f

    int t0 = blockIdx.x * CHUNK + threadIdx.x;
    int w0 = t0 >> 3;                       // input word index, iteration 0
    int c0 = (t0 & 7) * 4;                  // loop-invariant bit-channel base

    if (t0 + (ITERS - 1) * THREADS < n4) {
        // Fast path: all ITERS iterations in bounds. Front-batch the loads.
        uint32_t u[ITERS];
        #pragma unroll
        for (int i = 0; i < ITERS; i++)
            u[i] = __ldg(&x[w0 + i * WSTRIDE]);   // 8 lanes share one word

        #pragma unroll
        for (int i = 0; i < ITERS; i++) {
            uint32_t base = u[i] << c0;     // bit 31 of base == channel c0
            float4 v;
            v.x = __uint_as_float( (base >> 31)       * ONE);
            v.y = __uint_as_float(((base >> 30) & 1u) * ONE);
            v.z = __uint_as_float(((base >> 29) & 1u) * ONE);
            v.w = __uint_as_float(((base >> 28) & 1u) * ONE);
            out[t0 + i * THREADS] = v;
        }
    } else {
        // Tail path (unused for the fixed 4096x512x32 shape).
        #pragma unroll
        for (int i = 0; i < ITERS; i++) {
            int t = t0 + i * THREADS;
            if (t < n4) {
                uint32_t base = __ldg(&x[t >> 3]) << c0;
                float4 v;
                v.x = __uint_as_float( (base >> 31)       * ONE);
                v.y = __uint_as_float(((base >> 30) & 1u) * ONE);
                v.z = __uint_as_float(((base >> 29) & 1u) * ONE);
                v.w = __uint_as_float(((base >> 28) & 1u) * ONE);
                out[t] = v;
            }
        }
    }
}

extern "C" void kernel_launch(void* const* d_in, const int* in_sizes, int n_in,
                              void* d_out, int out_size)
{
    const uint32_t* x = (const uint32_t*)d_in[0];
    float4* out = (float4*)d_out;

    int n4 = out_size / 4;                  // 16,777,216 for 4096x512x32
    int blocks = (n4 + CHUNK - 1) / CHUNK;  // 16384

    base_encoder_kernel<<<blocks, THREADS>>>(x, out, n4);
}